// round 12
// baseline (speedup 1.0000x reference)
#include <cuda_runtime.h>

#define BDIM    32
#define CDIM    256
#define HW      4096
#define HW4     1024                 // float4 per plane
#define NPLANES (BDIM * CDIM)        // 8192 planes of 16 KB
#define KTAPS   3
#define KC      (KTAPS * CDIM)       // 768
#define NOUT    (BDIM * KC)          // 24576 filter outputs
#define BN_EPS  1e-5f
#define NCACHE  13                   // planes cached in smem per CTA (13*16KB=208KB)
#define TPB     256

__device__ float        g_gapsum[NPLANES];   // raw plane sums (zeroed per launch)
__device__ float        g_filt[NOUT];        // sigmoid filters
__device__ unsigned int g_bar;               // monotonic grid-barrier counter

// Grid barrier: monotonic counter, no reset needed across graph replays.
// Safe because grid == SM count and 1 CTA/SM (all CTAs co-resident).
__device__ __forceinline__ void grid_barrier(int G) {
    __syncthreads();
    if (threadIdx.x == 0) {
        __threadfence();
        unsigned old = atomicAdd(&g_bar, 1u);
        unsigned target = old - (old % (unsigned)G) + (unsigned)G;
        while (*(volatile unsigned*)&g_bar < target) __nanosleep(64);
        __threadfence();
    }
    __syncthreads();
}

// Load one plane's 4 float4s for this thread, from smem cache if resident.
__device__ __forceinline__ void load_plane(const float4* __restrict__ x4,
                                           const float4* __restrict__ cache,
                                           int start, int q, int t, float4 v[4]) {
    const int ci = q - start;
    if (ci >= 0 && ci < NCACHE) {
#pragma unroll
        for (int k = 0; k < 4; ++k) v[k] = cache[ci * HW4 + t + k * 256];
    } else {
#pragma unroll
        for (int k = 0; k < 4; ++k) v[k] = x4[(size_t)q * HW4 + t + k * 256];
    }
}

__global__ __launch_bounds__(TPB, 1)
void fused_kernel(const float* __restrict__ x,
                  const float* __restrict__ conv_w,
                  const float* __restrict__ bn_w,
                  const float* __restrict__ bn_b,
                  const float* __restrict__ bn_mean,
                  const float* __restrict__ bn_var,
                  const float* __restrict__ gamma,
                  const float* __restrict__ beta,
                  float* __restrict__ out, int G) {
    extern __shared__ __align__(16) float4 cache[];      // NCACHE*HW4 float4
    __shared__ __align__(16) float sg[CDIM];
    const int cta = blockIdx.x;
    const int t   = threadIdx.x;
    const int start = (int)(((long long)cta * NPLANES) / G);
    const int end   = (int)(((long long)(cta + 1) * NPLANES) / G);
    const float4* __restrict__ x4 = reinterpret_cast<const float4*>(x);
    float4* __restrict__ o4 = reinterpret_cast<float4*>(out);

    // Zero my gap accumulators (replay-safe), then accumulate via atomics.
    for (int p = start + t; p < end; p += TPB) g_gapsum[p] = 0.0f;
    __syncthreads();

    // ---- Phase 1: GAP read pass; park first NCACHE planes in smem ----
    for (int p = start; p < end; ++p) {
        const float4* pp = x4 + (size_t)p * HW4;
        float4 v0 = pp[t], v1 = pp[t + 256], v2 = pp[t + 512], v3 = pp[t + 768];
        const int ci = p - start;
        if (ci < NCACHE) {
            cache[ci * HW4 + t]       = v0;
            cache[ci * HW4 + t + 256] = v1;
            cache[ci * HW4 + t + 512] = v2;
            cache[ci * HW4 + t + 768] = v3;
        }
        float s = ((v0.x + v0.y) + (v0.z + v0.w)) + ((v1.x + v1.y) + (v1.z + v1.w))
                + ((v2.x + v2.y) + (v2.z + v2.w)) + ((v3.x + v3.y) + (v3.z + v3.w));
#pragma unroll
        for (int o = 16; o; o >>= 1) s += __shfl_xor_sync(0xffffffffu, s, o);
        if ((t & 31) == 0) atomicAdd(&g_gapsum[p], s);   // 8 REDG/plane, same-CTA only
    }

    grid_barrier(G);

    // ---- Phase 2: filters (warp-per-output GEMV + BN + sigmoid) ----
    {
        const int olo = (int)(((long long)cta * NOUT) / G);
        const int ohi = (int)(((long long)(cta + 1) * NOUT) / G);
        const int blo = olo / KC, bhi = (ohi - 1) / KC;
        const int warp = t >> 5, lid = t & 31;
        for (int b = blo; b <= bhi; ++b) {
            sg[t] = g_gapsum[b * CDIM + t] * (1.0f / (float)HW);
            __syncthreads();
            const float4 g1 = *reinterpret_cast<const float4*>(&sg[4 * lid]);
            const float4 g2 = *reinterpret_cast<const float4*>(&sg[128 + 4 * lid]);
            const int rlo = (olo > b * KC) ? (olo - b * KC) : 0;
            const int rhi = (ohi < (b + 1) * KC) ? (ohi - b * KC) : KC;
            for (int r = rlo + warp; r < rhi; r += 8) {
                const float4* __restrict__ w4 =
                    reinterpret_cast<const float4*>(conv_w + (size_t)r * CDIM);
                const float4 wa = w4[lid];
                const float4 wb = w4[lid + 32];
                float acc = wa.x * g1.x;
                acc = fmaf(wa.y, g1.y, acc);
                acc = fmaf(wa.z, g1.z, acc);
                acc = fmaf(wa.w, g1.w, acc);
                acc = fmaf(wb.x, g2.x, acc);
                acc = fmaf(wb.y, g2.y, acc);
                acc = fmaf(wb.z, g2.z, acc);
                acc = fmaf(wb.w, g2.w, acc);
#pragma unroll
                for (int off = 16; off; off >>= 1)
                    acc += __shfl_xor_sync(0xffffffffu, acc, off);
                if (lid == 0) {
                    float f = (acc - bn_mean[r]) * rsqrtf(bn_var[r] + BN_EPS) * bn_w[r]
                              + bn_b[r];
                    g_filt[b * KC + r] = 1.0f / (1.0f + __expf(-f));
                }
            }
            __syncthreads();
        }
    }

    grid_barrier(G);

    // ---- Phase 3: dynamic 3-tap conv + affine residual (rolling registers) ----
    int p = start;
    while (p < end) {
        const int b      = p >> 8;
        const int segEnd = ((b + 1) << 8) < end ? ((b + 1) << 8) : end;
        const float* __restrict__ fb = g_filt + b * KC;
        float4 xm[4], xc[4], xn[4];
        {
            const int c = p & 255;
            load_plane(x4, cache, start, p, t, xc);
            const int qm = (c == 0) ? p + 1 : p - 1;
            load_plane(x4, cache, start, qm, t, xm);
        }
        for (; p < segEnd; ++p) {
            const int c = p & 255;
            if (c == 255) {
#pragma unroll
                for (int k = 0; k < 4; ++k) xn[k] = xm[k];   // reflect: x[254]
            } else {
                load_plane(x4, cache, start, p + 1, t, xn);
            }
            const float f0 = fb[c], f1 = fb[CDIM + c], f2 = fb[2 * CDIM + c];
            const float gm = gamma[c], bt = beta[c];
            float4* op = o4 + (size_t)p * HW4;
#pragma unroll
            for (int k = 0; k < 4; ++k) {
                float4 r;
                r.x = fmaf(fmaf(f0, xm[k].x, fmaf(f1, xc[k].x, f2 * xn[k].x)), gm, xc[k].x * bt);
                r.y = fmaf(fmaf(f0, xm[k].y, fmaf(f1, xc[k].y, f2 * xn[k].y)), gm, xc[k].y * bt);
                r.z = fmaf(fmaf(f0, xm[k].z, fmaf(f1, xc[k].z, f2 * xn[k].z)), gm, xc[k].z * bt);
                r.w = fmaf(fmaf(f0, xm[k].w, fmaf(f1, xc[k].w, f2 * xn[k].w)), gm, xc[k].w * bt);
                __stcs(&op[t + k * 256], r);
            }
#pragma unroll
            for (int k = 0; k < 4; ++k) { xm[k] = xc[k]; xc[k] = xn[k]; }
        }
    }
}

// ---------------------------------------------------------------------------
// Launch: ONE persistent kernel, grid = SM count (1 CTA/SM co-residency).
// Input order: x, conv_w, bn_w, bn_b, bn_mean, bn_var, gamma, beta
// ---------------------------------------------------------------------------
extern "C" void kernel_launch(void* const* d_in, const int* in_sizes, int n_in,
                              void* d_out, int out_size) {
    const float* x       = (const float*)d_in[0];
    const float* conv_w  = (const float*)d_in[1];
    const float* bn_w    = (const float*)d_in[2];
    const float* bn_b    = (const float*)d_in[3];
    const float* bn_mean = (const float*)d_in[4];
    const float* bn_var  = (const float*)d_in[5];
    const float* gamma   = (const float*)d_in[6];
    const float* beta    = (const float*)d_in[7];
    float* out = (float*)d_out;

    static int G = 0;
    static bool attr_set = false;
    const int dynSmem = NCACHE * HW4 * (int)sizeof(float4);   // 212992 B
    if (!attr_set) {
        cudaFuncSetAttribute(fused_kernel,
                             cudaFuncAttributeMaxDynamicSharedMemorySize, dynSmem);
        if (cudaDeviceGetAttribute(&G, cudaDevAttrMultiProcessorCount, 0)
                != cudaSuccess || G <= 0)
            G = 148;
        attr_set = true;
    }

    fused_kernel<<<G, TPB, dynSmem>>>(x, conv_w, bn_w, bn_b, bn_mean, bn_var,
                                      gamma, beta, out, G);
}

// round 15
// speedup vs baseline: 1.3103x; 1.3103x over previous
#include <cuda_runtime.h>

#define BDIM    32
#define CDIM    256
#define HW      4096
#define HW4     1024                 // float4 per plane
#define NPLANES (BDIM * CDIM)        // 8192 planes of 16 KB
#define KTAPS   3
#define KC      (KTAPS * CDIM)       // 768
#define NOUT    (BDIM * KC)          // 24576 filter outputs
#define BN_EPS  1e-5f
#define NCACHE  13                   // planes cached in smem per CTA (13*16KB=208KB)
#define TPB     1024                 // 32 warps/SM (was 8 — the R12 failure)

__device__ float        g_gapsum[NPLANES];   // raw plane sums
__device__ float        g_filt[NOUT];        // sigmoid filters
__device__ unsigned int g_bar;               // monotonic grid-barrier counter

// Grid barrier: monotonic counter, replay-safe (no reset). Valid because
// grid == SM count and 1 CTA/SM (guaranteed co-residency).
__device__ __forceinline__ void grid_barrier(int G) {
    __syncthreads();
    if (threadIdx.x == 0) {
        __threadfence();
        unsigned old = atomicAdd(&g_bar, 1u);
        unsigned target = old - (old % (unsigned)G) + (unsigned)G;
        while (*(volatile unsigned*)&g_bar < target) __nanosleep(64);
        __threadfence();
    }
    __syncthreads();
}

__global__ __launch_bounds__(TPB, 1)
void fused_kernel(const float* __restrict__ x,
                  const float* __restrict__ conv_w,
                  const float* __restrict__ bn_w,
                  const float* __restrict__ bn_b,
                  const float* __restrict__ bn_mean,
                  const float* __restrict__ bn_var,
                  const float* __restrict__ gamma,
                  const float* __restrict__ beta,
                  float* __restrict__ out, int G) {
    extern __shared__ __align__(16) float4 cache[];      // NCACHE * HW4 float4
    __shared__ __align__(16) float sg[CDIM];
    const int cta  = blockIdx.x;
    const int t    = threadIdx.x;
    const int warp = t >> 5;
    const int lid  = t & 31;
    const int start = (int)(((long long)cta * NPLANES) / G);
    const int end   = (int)(((long long)(cta + 1) * NPLANES) / G);
    const float4* __restrict__ x4 = reinterpret_cast<const float4*>(x);
    float4* __restrict__ o4 = reinterpret_cast<float4*>(out);

    // ---- Phase 1: warp-per-plane GAP (no atomics). Warps 0..NCACHE-1 park
    // their first plane in smem while reducing it. ----
    for (int p = start + warp; p < end; p += 32) {
        const float4* __restrict__ pp = x4 + (size_t)p * HW4;
        const int ci = p - start;
        float s = 0.0f;
        if (ci < NCACHE) {
            float4* __restrict__ cp = cache + ci * HW4;
#pragma unroll 8
            for (int i = 0; i < 32; ++i) {
                float4 v = pp[lid + i * 32];
                cp[lid + i * 32] = v;
                s += (v.x + v.y) + (v.z + v.w);
            }
        } else {
#pragma unroll 8
            for (int i = 0; i < 32; ++i) {
                float4 v = pp[lid + i * 32];
                s += (v.x + v.y) + (v.z + v.w);
            }
        }
#pragma unroll
        for (int o = 16; o; o >>= 1) s += __shfl_xor_sync(0xffffffffu, s, o);
        if (lid == 0) g_gapsum[p] = s;
    }

    grid_barrier(G);

    // ---- Phase 2: filters (warp-per-output GEMV + BN + sigmoid) ----
    {
        const int olo = (int)(((long long)cta * NOUT) / G);
        const int ohi = (int)(((long long)(cta + 1) * NOUT) / G);
        const int blo = olo / KC, bhi = (ohi - 1) / KC;
        for (int b = blo; b <= bhi; ++b) {
            if (t < CDIM) sg[t] = g_gapsum[b * CDIM + t] * (1.0f / (float)HW);
            __syncthreads();
            const float4 g1 = *reinterpret_cast<const float4*>(&sg[4 * lid]);
            const float4 g2 = *reinterpret_cast<const float4*>(&sg[128 + 4 * lid]);
            const int rlo = (olo > b * KC) ? (olo - b * KC) : 0;
            const int rhi = (ohi < (b + 1) * KC) ? (ohi - b * KC) : KC;
            for (int r = rlo + warp; r < rhi; r += 32) {
                const float4* __restrict__ w4 =
                    reinterpret_cast<const float4*>(conv_w + (size_t)r * CDIM);
                const float4 wa = w4[lid];
                const float4 wb = w4[lid + 32];
                float acc = wa.x * g1.x;
                acc = fmaf(wa.y, g1.y, acc);
                acc = fmaf(wa.z, g1.z, acc);
                acc = fmaf(wa.w, g1.w, acc);
                acc = fmaf(wb.x, g2.x, acc);
                acc = fmaf(wb.y, g2.y, acc);
                acc = fmaf(wb.z, g2.z, acc);
                acc = fmaf(wb.w, g2.w, acc);
#pragma unroll
                for (int off = 16; off; off >>= 1)
                    acc += __shfl_xor_sync(0xffffffffu, acc, off);
                if (lid == 0) {
                    float f = (acc - bn_mean[r]) * rsqrtf(bn_var[r] + BN_EPS) * bn_w[r]
                              + bn_b[r];
                    g_filt[b * KC + r] = 1.0f / (1.0f + __expf(-f));
                }
            }
            __syncthreads();
        }
    }

    grid_barrier(G);

    // ---- Phase 3: dynamic 3-tap conv + affine residual. Thread t owns
    // float4-slot t of every plane; rolling registers (1 load + 1 store
    // per element; cached planes read from smem). ----
    int p = start;
    while (p < end) {
        const int b      = p >> 8;
        const int segEnd = ((b + 1) << 8) < end ? ((b + 1) << 8) : end;
        const float* __restrict__ fb = g_filt + b * KC;
        float4 xm, xc, xn;
        {
            const int c  = p & 255;
            const int ci = p - start;
            xc = (ci < NCACHE) ? cache[ci * HW4 + t]
                               : __ldcs(&x4[(size_t)p * HW4 + t]);
            const int qm  = (c == 0) ? p + 1 : p - 1;
            const int cim = qm - start;
            xm = (cim >= 0 && cim < NCACHE) ? cache[cim * HW4 + t]
                                            : __ldcs(&x4[(size_t)qm * HW4 + t]);
        }
#pragma unroll 4
        for (; p < segEnd; ++p) {
            const int c = p & 255;
            if (c == 255) {
                xn = xm;                                 // reflect: x[254]
            } else {
                const int cin = p + 1 - start;
                xn = (cin < NCACHE) ? cache[cin * HW4 + t]
                                    : __ldcs(&x4[(size_t)(p + 1) * HW4 + t]);
            }
            const float f0 = fb[c], f1 = fb[CDIM + c], f2 = fb[2 * CDIM + c];
            const float gm = gamma[c], bt = beta[c];
            float4 r;
            r.x = fmaf(fmaf(f0, xm.x, fmaf(f1, xc.x, f2 * xn.x)), gm, xc.x * bt);
            r.y = fmaf(fmaf(f0, xm.y, fmaf(f1, xc.y, f2 * xn.y)), gm, xc.y * bt);
            r.z = fmaf(fmaf(f0, xm.z, fmaf(f1, xc.z, f2 * xn.z)), gm, xc.z * bt);
            r.w = fmaf(fmaf(f0, xm.w, fmaf(f1, xc.w, f2 * xn.w)), gm, xc.w * bt);
            __stcs(&o4[(size_t)p * HW4 + t], r);
            xm = xc;
            xc = xn;
        }
    }
}

// ---------------------------------------------------------------------------
// Launch: ONE persistent kernel, grid = SM count (1 CTA/SM co-residency).
// Input order: x, conv_w, bn_w, bn_b, bn_mean, bn_var, gamma, beta
// ---------------------------------------------------------------------------
extern "C" void kernel_launch(void* const* d_in, const int* in_sizes, int n_in,
                              void* d_out, int out_size) {
    const float* x       = (const float*)d_in[0];
    const float* conv_w  = (const float*)d_in[1];
    const float* bn_w    = (const float*)d_in[2];
    const float* bn_b    = (const float*)d_in[3];
    const float* bn_mean = (const float*)d_in[4];
    const float* bn_var  = (const float*)d_in[5];
    const float* gamma   = (const float*)d_in[6];
    const float* beta    = (const float*)d_in[7];
    float* out = (float*)d_out;

    static int G = 0;
    static bool attr_set = false;
    const int dynSmem = NCACHE * HW4 * (int)sizeof(float4);   // 212992 B
    if (!attr_set) {
        cudaFuncSetAttribute(fused_kernel,
                             cudaFuncAttributeMaxDynamicSharedMemorySize, dynSmem);
        if (cudaDeviceGetAttribute(&G, cudaDevAttrMultiProcessorCount, 0)
                != cudaSuccess || G <= 0)
            G = 148;
        attr_set = true;
    }

    fused_kernel<<<G, TPB, dynSmem>>>(x, conv_w, bn_w, bn_b, bn_mean, bn_var,
                                      gamma, beta, out, G);
}

// round 16
// speedup vs baseline: 1.4272x; 1.0893x over previous
#include <cuda_runtime.h>

// Problem constants (fixed by the reference)
#define BDIM   32
#define CDIM   256
#define HW     4096          // 64*64
#define HW4    1024          // float4 per plane
#define KTAPS  3
#define KC     (KTAPS * CDIM)   // 768
#define BN_EPS 1e-5f

#define PIN_BYTES (48u * 1024u * 1024u)   // persisting-L2 window over head of x

// Scratch (allocation-free rule: __device__ globals)
__device__ float g_gap [BDIM * CDIM];          // [B, C] plane means
__device__ float g_filt[BDIM * KC];            // [B, 3, C] sigmoid filters

// ---------------------------------------------------------------------------
// Kernel A: global average pool — best measured shape: one plane per
// 128-thread block, grid 8192, ascending traversal.
// ---------------------------------------------------------------------------
__global__ void gap_kernel(const float* __restrict__ x) {
    const int plane = blockIdx.x;                       // 0 .. B*C-1
    const float4* __restrict__ p =
        reinterpret_cast<const float4*>(x + (size_t)plane * HW);
    const int t = threadIdx.x;                          // 128 threads
    float s = 0.0f;
#pragma unroll
    for (int i = 0; i < 8; ++i) {
        float4 v = p[t + i * 128];
        s += (v.x + v.y) + (v.z + v.w);
    }
#pragma unroll
    for (int o = 16; o; o >>= 1)
        s += __shfl_xor_sync(0xffffffffu, s, o);
    __shared__ float ws[4];
    if ((t & 31) == 0) ws[t >> 5] = s;
    __syncthreads();
    if (t == 0)
        g_gap[plane] = (ws[0] + ws[1] + ws[2] + ws[3]) * (1.0f / (float)HW);
}

// ---------------------------------------------------------------------------
// Kernel B: warp-per-output GEMV (unchanged). PDL-synced on gap_kernel.
// ---------------------------------------------------------------------------
__global__ __launch_bounds__(256)
void filt_kernel(const float* __restrict__ conv_w,
                 const float* __restrict__ bn_w,
                 const float* __restrict__ bn_b,
                 const float* __restrict__ bn_mean,
                 const float* __restrict__ bn_var) {
    const int b    = blockIdx.y;
    const int warp = threadIdx.x >> 5;      // 0..7
    const int lid  = threadIdx.x & 31;

#if __CUDA_ARCH__ >= 900
    cudaGridDependencySynchronize();        // wait for gap_kernel's g_gap
#endif

    __shared__ __align__(16) float sg[CDIM];
    for (int i = threadIdx.x; i < CDIM; i += 256)
        sg[i] = g_gap[b * CDIM + i];
    __syncthreads();

    const float4 g1 = *reinterpret_cast<const float4*>(&sg[4 * lid]);
    const float4 g2 = *reinterpret_cast<const float4*>(&sg[128 + 4 * lid]);

#pragma unroll
    for (int i = 0; i < 16; ++i) {
        const int o = blockIdx.x * 128 + warp * 16 + i;  // output row
        const float4* __restrict__ w4 =
            reinterpret_cast<const float4*>(conv_w + (size_t)o * CDIM);
        const float4 wa = w4[lid];        // c = 4*lid .. 4*lid+3
        const float4 wb = w4[lid + 32];   // c = 128+4*lid ..
        float acc = wa.x * g1.x;
        acc = fmaf(wa.y, g1.y, acc);
        acc = fmaf(wa.z, g1.z, acc);
        acc = fmaf(wa.w, g1.w, acc);
        acc = fmaf(wb.x, g2.x, acc);
        acc = fmaf(wb.y, g2.y, acc);
        acc = fmaf(wb.z, g2.z, acc);
        acc = fmaf(wb.w, g2.w, acc);
#pragma unroll
        for (int off = 16; off; off >>= 1)
            acc += __shfl_xor_sync(0xffffffffu, acc, off);
        if (lid == 0) {
            float f = (acc - bn_mean[o]) * rsqrtf(bn_var[o] + BN_EPS) * bn_w[o]
                      + bn_b[o];
            g_filt[b * KC + o] = 1.0f / (1.0f + __expf(-f));
        }
    }
}

// ---------------------------------------------------------------------------
// Kernel C: main fused pass (R6 best config: CSEG=32, ascending order).
// Plain loads (so the persisting window applies), __stcs stores.
// ---------------------------------------------------------------------------
#define CSEG     32
#define CTHREADS 128

__global__ __launch_bounds__(CTHREADS)
void main_kernel(const float* __restrict__ x,
                 const float* __restrict__ gamma,
                 const float* __restrict__ beta,
                 float* __restrict__ out) {
    const int t   = threadIdx.x;
    const int b   = blockIdx.z;
    const int c0  = blockIdx.y * CSEG;
    const int hw4 = blockIdx.x * CTHREADS + t;          // float4 index in plane

    const int STRIDE = HW4;                             // float4 per channel
    const float4* __restrict__ xb =
        reinterpret_cast<const float4*>(x) + (size_t)b * CDIM * STRIDE + hw4;
    float4* __restrict__ ob =
        reinterpret_cast<float4*>(out) + (size_t)b * CDIM * STRIDE + hw4;

    // Seed rolling registers early (independent of filt_kernel's output).
    const int cm = (c0 == 0) ? 1 : (c0 - 1);
    float4 xm = xb[(size_t)cm * STRIDE];
    float4 xc = xb[(size_t)c0 * STRIDE];

#if __CUDA_ARCH__ >= 900
    cudaGridDependencySynchronize();        // wait for filt_kernel's g_filt
#endif

    __shared__ float sf0[CSEG], sf1[CSEG], sf2[CSEG], sgm[CSEG], sbt[CSEG];
    if (t < CSEG) {
        const int c = c0 + t;
        const float* __restrict__ fb = g_filt + b * KC;
        sf0[t] = fb[c];
        sf1[t] = fb[CDIM + c];
        sf2[t] = fb[2 * CDIM + c];
        sgm[t] = gamma[c];
        sbt[t] = beta[c];
    }
    __syncthreads();

#pragma unroll 8
    for (int c = c0; c < c0 + CSEG; ++c) {
        const int cn = (c == CDIM - 1) ? (CDIM - 2) : (c + 1);
        float4 xn = xb[(size_t)cn * STRIDE];
        const int ci = c - c0;
        const float f0 = sf0[ci], f1 = sf1[ci], f2 = sf2[ci];
        const float gm = sgm[ci], bt = sbt[ci];
        float4 r;
        r.x = fmaf(fmaf(f0, xm.x, fmaf(f1, xc.x, f2 * xn.x)), gm, xc.x * bt);
        r.y = fmaf(fmaf(f0, xm.y, fmaf(f1, xc.y, f2 * xn.y)), gm, xc.y * bt);
        r.z = fmaf(fmaf(f0, xm.z, fmaf(f1, xc.z, f2 * xn.z)), gm, xc.z * bt);
        r.w = fmaf(fmaf(f0, xm.w, fmaf(f1, xc.w, f2 * xn.w)), gm, xc.w * bt);
        __stcs(&ob[(size_t)c * STRIDE], r);             // evict-first store
        xm = xc;
        xc = xn;
    }
}

// ---------------------------------------------------------------------------
// Launch (graph-capturable). PDL chains gap -> filt -> main. gap and main
// carry a persisting-L2 access-policy window over the head of x (per-launch
// attribute; no device limits touched — inert if carveout is 0).
// Input order: x, conv_w, bn_w, bn_b, bn_mean, bn_var, gamma, beta
// ---------------------------------------------------------------------------
extern "C" void kernel_launch(void* const* d_in, const int* in_sizes, int n_in,
                              void* d_out, int out_size) {
    const float* x       = (const float*)d_in[0];
    const float* conv_w  = (const float*)d_in[1];
    const float* bn_w    = (const float*)d_in[2];
    const float* bn_b    = (const float*)d_in[3];
    const float* bn_mean = (const float*)d_in[4];
    const float* bn_var  = (const float*)d_in[5];
    const float* gamma   = (const float*)d_in[6];
    const float* beta    = (const float*)d_in[7];
    float* out = (float*)d_out;

    cudaAccessPolicyWindow win = {};
    win.base_ptr  = (void*)x;
    win.num_bytes = PIN_BYTES;
    win.hitRatio  = 1.0f;
    win.hitProp   = cudaAccessPropertyPersisting;
    win.missProp  = cudaAccessPropertyStreaming;

    {   // gap_kernel: populate the persisting window while reducing
        cudaLaunchAttribute attrs[1];
        attrs[0].id = cudaLaunchAttributeAccessPolicyWindow;
        attrs[0].val.accessPolicyWindow = win;
        cudaLaunchConfig_t cfg = {};
        cfg.gridDim  = dim3(BDIM * CDIM, 1, 1);
        cfg.blockDim = dim3(128, 1, 1);
        cfg.stream   = 0;
        cfg.attrs    = attrs;
        cfg.numAttrs = 1;
        cudaLaunchKernelEx(&cfg, gap_kernel, x);
    }
    {   // filt_kernel with PDL
        cudaLaunchAttribute attrs[1];
        attrs[0].id = cudaLaunchAttributeProgrammaticStreamSerialization;
        attrs[0].val.programmaticStreamSerializationAllowed = 1;
        cudaLaunchConfig_t cfg = {};
        cfg.gridDim  = dim3(KC / 128, BDIM, 1);
        cfg.blockDim = dim3(256, 1, 1);
        cfg.stream   = 0;
        cfg.attrs    = attrs;
        cfg.numAttrs = 1;
        cudaLaunchKernelEx(&cfg, filt_kernel,
                           conv_w, bn_w, bn_b, bn_mean, bn_var);
    }
    {   // main_kernel with PDL + the same persisting window (reads hit L2)
        cudaLaunchAttribute attrs[2];
        attrs[0].id = cudaLaunchAttributeProgrammaticStreamSerialization;
        attrs[0].val.programmaticStreamSerializationAllowed = 1;
        attrs[1].id = cudaLaunchAttributeAccessPolicyWindow;
        attrs[1].val.accessPolicyWindow = win;
        cudaLaunchConfig_t cfg = {};
        cfg.gridDim  = dim3(HW4 / CTHREADS, CDIM / CSEG, BDIM);
        cfg.blockDim = dim3(CTHREADS, 1, 1);
        cfg.stream   = 0;
        cfg.attrs    = attrs;
        cfg.numAttrs = 2;
        cudaLaunchKernelEx(&cfg, main_kernel, x, gamma, beta, out);
    }
}